// round 2
// baseline (speedup 1.0000x reference)
#include <cuda_runtime.h>
#include <math.h>

#define NB 148
#define NT 512

#define Bz 64
#define Sz 64
#define Iz 512
#define Cz 512
#define Hz 1024
#define Dz 512
#define KYz 32000
#define Mz 512
#define H3z 3072

// ---------------- device scratch (static; allocated at module load) ----------------
__device__ __align__(128) float g_Uh[4096 * 512];        // (B*S, C)
__device__ __align__(128) float g_WihT[512 * 3072];      // W_ih^T (C, 3H)
__device__ __align__(128) float g_WhhT[1024 * 3072];     // W_hh^T (H, 3H)
__device__ __align__(128) float g_s[2][64 * 1024];       // hidden state ping-pong
__device__ __align__(128) float g_yE[64 * 512];          // y @ Ey_t
__device__ __align__(128) float g_ctx[64 * 512];
__device__ __align__(128) float g_wsbp[32][64 * 512];    // Wsb split-K partials
__device__ __align__(128) float g_gip[4][64 * 3072];     // gi partials
__device__ __align__(128) float g_ghp[8][64 * 3072];     // gh partials
__device__ __align__(128) float g_tp[16][64 * 1024];     // t partials (U_o 0-7, V_o 8-11, C_o 12-15)
__device__ __align__(128) float g_tmax[64 * 512];
__device__ __align__(128) float g_lg[64 * 32000];        // logits
__device__ __align__(128) float g_yep[50][64 * 512];     // yE split-K partials

// ---------------- software grid barrier ----------------
__device__ unsigned g_cnt = 0;
__device__ volatile unsigned g_gen = 0;

__device__ __forceinline__ void gsync() {
    __syncthreads();
    if (threadIdx.x == 0) {
        unsigned gen = g_gen;
        __threadfence();                       // flush this SM's stores (CCTL.IVALL on sm_103a)
        if (atomicAdd(&g_cnt, 1u) == NB - 1u) {
            atomicExch(&g_cnt, 0u);
            __threadfence();
            g_gen = gen + 1u;
        } else {
            while (g_gen == gen) __nanosleep(64);
            __threadfence();                   // invalidate L1 so fresh data is seen
        }
    }
    __syncthreads();
}

// ---------------- 64x128 tile GEMM (NN), 512 threads, 4x4 micro ----------------
// C tile rows [m0, m0+64), cols [n0, n0+128), K range [k0, k0+kc), kc % 16 == 0.
__device__ void gemm_tile(const float* __restrict__ A, int lda,
                          const float* __restrict__ B, int ldb,
                          float* __restrict__ C, int ldc,
                          int m0, int n0, int k0, int kc,
                          float* __restrict__ As, float* __restrict__ Bs) {
    const int tid  = threadIdx.x;
    const int rg   = (tid >> 5) << 2;     // output row base (0..60)
    const int cg   = (tid & 31) << 2;     // output col base (0..124)
    const int arow = tid >> 3;            // A loader: row (0..63)
    const int akq  = (tid & 7) << 1;      // A loader: k pair (0..14)
    const int bkr  = tid >> 5;            // B loader: k (0..15)
    const int bc4  = (tid & 31) << 2;     // B loader: col4

    float acc[4][4];
#pragma unroll
    for (int r = 0; r < 4; r++)
#pragma unroll
        for (int c = 0; c < 4; c++) acc[r][c] = 0.f;

    const float* Ap = A + (size_t)(m0 + arow) * lda + (k0 + akq);
    const float* Bp = B + (size_t)(k0 + bkr) * ldb + (n0 + bc4);

    for (int ks = 0; ks < kc; ks += 16) {
        float2 av = *(const float2*)Ap;
        float4 bvv = *(const float4*)Bp;
        Ap += 16;
        Bp += (size_t)16 * ldb;
        __syncthreads();
        As[akq * 64 + arow]       = av.x;
        As[(akq + 1) * 64 + arow] = av.y;
        *(float4*)(Bs + bkr * 128 + bc4) = bvv;
        __syncthreads();
#pragma unroll
        for (int kk = 0; kk < 16; kk++) {
            float4 a4 = *(const float4*)(As + kk * 64 + rg);
            float4 b4 = *(const float4*)(Bs + kk * 128 + cg);
            const float aa[4] = {a4.x, a4.y, a4.z, a4.w};
            const float bb[4] = {b4.x, b4.y, b4.z, b4.w};
#pragma unroll
            for (int r = 0; r < 4; r++)
#pragma unroll
                for (int c = 0; c < 4; c++)
                    acc[r][c] = fmaf(aa[r], bb[c], acc[r][c]);
        }
    }
#pragma unroll
    for (int r = 0; r < 4; r++) {
        float4 o = make_float4(acc[r][0], acc[r][1], acc[r][2], acc[r][3]);
        *(float4*)(C + (size_t)(m0 + rg + r) * ldc + (n0 + cg)) = o;
    }
}

__device__ __forceinline__ float block_max(float v, float* red) {
#pragma unroll
    for (int o = 16; o > 0; o >>= 1) v = fmaxf(v, __shfl_down_sync(0xffffffffu, v, o));
    int w = threadIdx.x >> 5;
    if ((threadIdx.x & 31) == 0) red[w] = v;
    __syncthreads();
    float r = red[0];
#pragma unroll
    for (int i = 1; i < 16; i++) r = fmaxf(r, red[i]);
    __syncthreads();
    return r;
}

__device__ __forceinline__ float block_sum(float v, float* red) {
#pragma unroll
    for (int o = 16; o > 0; o >>= 1) v += __shfl_down_sync(0xffffffffu, v, o);
    int w = threadIdx.x >> 5;
    if ((threadIdx.x & 31) == 0) red[w] = v;
    __syncthreads();
    float r = 0.f;
#pragma unroll
    for (int i = 0; i < 16; i++) r += red[i];
    __syncthreads();
    return r;
}

// ---------------- single persistent kernel ----------------
__global__ __launch_bounds__(NT, 1) void dec_kernel(
    const float* __restrict__ x,    const float* __restrict__ Ey_t,
    const float* __restrict__ W,    const float* __restrict__ U,
    const float* __restrict__ bvec, const float* __restrict__ v,
    const float* __restrict__ W_ih, const float* __restrict__ W_hh,
    const float* __restrict__ b_ih, const float* __restrict__ b_hh,
    const float* __restrict__ U_o,  const float* __restrict__ V_o,
    const float* __restrict__ C_o,  const float* __restrict__ W_o,
    float* __restrict__ out) {
    __shared__ float As[16 * 64];
    __shared__ float Bs[16 * 128];
    __shared__ float s_wsb[512];
    __shared__ float s_e[64];
    __shared__ float s_a[64];
    __shared__ float s_red[16];

    const int tid = threadIdx.x;
    const int bid = blockIdx.x;
    const int gth = bid * NT + tid;
    const int GSTRIDE = NB * NT;

    // ---- prep: zeros, weight transposes, U_h = x @ U ----
    for (int i = gth; i < 64 * 1024; i += GSTRIDE) g_s[0][i] = 0.f;
    for (int i = gth; i < 64 * 512; i += GSTRIDE) g_yE[i] = 0.f;
    for (int i = gth; i < 512 * 3072; i += GSTRIDE) {
        int k = i / 3072, n = i % 3072;
        g_WihT[i] = W_ih[(size_t)n * 512 + k];
    }
    for (int i = gth; i < 1024 * 3072; i += GSTRIDE) {
        int k = i / 3072, n = i % 3072;
        g_WhhT[i] = W_hh[(size_t)n * 1024 + k];
    }
    for (int j = bid; j < 256; j += NB) {   // 64 m-tiles x 4 n-tiles, K=512
        int mt = j >> 2, nt = j & 3;
        gemm_tile(x, 512, U, 512, g_Uh, 512, mt * 64, nt * 128, 0, 512, As, Bs);
    }
    gsync();

    for (int t = 0; t < Sz; t++) {
        const float* scur = g_s[t & 1];
        float* snxt = g_s[(t + 1) & 1];

        // ---- Phase A: Wsb split-K partials (+ yE reduce from prev step) ----
        for (int j = bid; j < 128; j += NB) {   // 32 k-chunks(32) x 4 n-tiles
            int ch = j >> 2, nt = j & 3;
            gemm_tile(scur, 1024, W, 512, g_wsbp[ch], 512, 0, nt * 128, ch * 32, 32, As, Bs);
        }
        if (t > 0) {
            for (int i = gth; i < 64 * 512; i += GSTRIDE) {
                float s = 0.f;
#pragma unroll
                for (int p = 0; p < 50; p++) s += g_yep[p][i];
                g_yE[i] = s;
            }
        }
        gsync();

        // ---- Phase B: attention (per-batch blocks): Wsb final, e, softmax, ctx ----
        for (int b = bid; b < 64; b += NB) {
            float wacc = bvec[tid];
#pragma unroll
            for (int p = 0; p < 32; p++) wacc += g_wsbp[p][b * 512 + tid];
            s_wsb[tid] = wacc;
            __syncthreads();
            int wid = tid >> 5, lane = tid & 31;
#pragma unroll
            for (int jj = 0; jj < 4; jj++) {
                int j = (wid << 2) + jj;
                const float* uh = g_Uh + (size_t)(b * 64 + j) * 512;
                float e = 0.f;
                for (int c = lane; c < 512; c += 32)
                    e += tanhf(s_wsb[c] + uh[c]) * v[c];
#pragma unroll
                for (int o = 16; o > 0; o >>= 1) e += __shfl_down_sync(0xffffffffu, e, o);
                if (lane == 0) s_e[j] = e;
            }
            __syncthreads();
            float mx = -1e30f;
#pragma unroll
            for (int j = 0; j < 64; j++) mx = fmaxf(mx, s_e[j]);
            if (tid < 64) s_a[tid] = expf(s_e[tid] - mx);
            __syncthreads();
            float ssum = 0.f;
#pragma unroll
            for (int j = 0; j < 64; j++) ssum += s_a[j];
            float inv = 1.f / ssum;
            const float* xb = x + (size_t)b * (64 * 512);
            float cacc = 0.f;
            for (int j = 0; j < 64; j++) cacc += s_a[j] * xb[j * 512 + tid];
            g_ctx[b * 512 + tid] = cacc * inv;
            __syncthreads();
        }
        gsync();

        // ---- Phase C: GRU gemms: gi = ctx@WihT (96 jobs), gh = s@WhhT (192 jobs) ----
        for (int j = bid; j < 288; j += NB) {
            if (j < 96) {
                int ch = j / 24, nt = j % 24;
                gemm_tile(g_ctx, 512, g_WihT, 3072, g_gip[ch], 3072, 0, nt * 128, ch * 128, 128, As, Bs);
            } else {
                int q = j - 96;
                int ch = q / 24, nt = q % 24;
                gemm_tile(scur, 1024, g_WhhT, 3072, g_ghp[ch], 3072, 0, nt * 128, ch * 128, 128, As, Bs);
            }
        }
        gsync();

        // ---- Phase D: gate combine -> s_new ----
        for (int i = gth; i < 64 * 1024; i += GSTRIDE) {
            int b = i >> 10, h = i & 1023;
            int base = b * 3072;
            float gr = b_ih[h], gz = b_ih[1024 + h], gn = b_ih[2048 + h];
            float hr = b_hh[h], hz = b_hh[1024 + h], hn = b_hh[2048 + h];
#pragma unroll
            for (int p = 0; p < 4; p++) {
                gr += g_gip[p][base + h];
                gz += g_gip[p][base + 1024 + h];
                gn += g_gip[p][base + 2048 + h];
            }
#pragma unroll
            for (int p = 0; p < 8; p++) {
                hr += g_ghp[p][base + h];
                hz += g_ghp[p][base + 1024 + h];
                hn += g_ghp[p][base + 2048 + h];
            }
            float r = 1.f / (1.f + expf(-(gr + hr)));
            float z = 1.f / (1.f + expf(-(gz + hz)));
            float n = tanhf(gn + r * hn);
            snxt[i] = (1.f - z) * n + z * scur[i];
        }
        gsync();

        // ---- Phase E: t = s_new@U_o + yE@V_o + ctx@C_o (partials) ----
        for (int j = bid; j < 128; j += NB) {
            if (j < 64) {
                int ch = j >> 3, nt = j & 7;
                gemm_tile(snxt, 1024, U_o, 1024, g_tp[ch], 1024, 0, nt * 128, ch * 128, 128, As, Bs);
            } else if (j < 96) {
                int q = j - 64;
                int ch = q >> 3, nt = q & 7;
                gemm_tile(g_yE, 512, V_o, 1024, g_tp[8 + ch], 1024, 0, nt * 128, ch * 128, 128, As, Bs);
            } else {
                int q = j - 96;
                int ch = q >> 3, nt = q & 7;
                gemm_tile(g_ctx, 512, C_o, 1024, g_tp[12 + ch], 1024, 0, nt * 128, ch * 128, 128, As, Bs);
            }
        }
        gsync();

        // ---- Phase F: reduce t partials + maxout -> tmax ----
        for (int i = gth; i < 64 * 512; i += GSTRIDE) {
            int b = i >> 9, d = i & 511;
            int base = b * 1024 + 2 * d;
            float t0 = 0.f, t1 = 0.f;
#pragma unroll
            for (int p = 0; p < 16; p++) {
                t0 += g_tp[p][base];
                t1 += g_tp[p][base + 1];
            }
            g_tmax[i] = fmaxf(t0, t1);
        }
        gsync();

        // ---- Phase G: logits = tmax @ W_o (250 tiles, K=512) ----
        for (int j = bid; j < 250; j += NB)
            gemm_tile(g_tmax, 512, W_o, 32000, g_lg, 32000, 0, j * 128, 0, 512, As, Bs);
        gsync();

        // ---- Phase H: vocab softmax -> out ----
        float* po = out + (size_t)t * (Bz * KYz);
        for (int b = bid; b < 64; b += NB) {
            const float* l = g_lg + (size_t)b * KYz;
            float mx = -1e30f;
            for (int k = tid; k < KYz; k += NT) mx = fmaxf(mx, l[k]);
            mx = block_max(mx, s_red);
            float s = 0.f;
            for (int k = tid; k < KYz; k += NT) s += expf(l[k] - mx);
            s = block_sum(s, s_red);
            float inv = 1.f / s;
            float* pb = po + (size_t)b * KYz;
            for (int k = tid; k < KYz; k += NT) pb[k] = expf(l[k] - mx) * inv;
            __syncthreads();
        }
        gsync();

        // ---- Phase I: yE partials = probs @ Ey_t (skip on last step) ----
        if (t < Sz - 1) {
            for (int j = bid; j < 200; j += NB) {   // 50 k-chunks(640) x 4 n-tiles
                int ch = j >> 2, nt = j & 3;
                gemm_tile(po, 32000, Ey_t, 512, g_yep[ch], 512, 0, nt * 128, ch * 640, 640, As, Bs);
            }
            gsync();
        }
    }
}

extern "C" void kernel_launch(void* const* d_in, const int* in_sizes, int n_in,
                              void* d_out, int out_size) {
    const float* x    = (const float*)d_in[0];
    const float* Ey_t = (const float*)d_in[1];
    const float* W    = (const float*)d_in[2];
    const float* U    = (const float*)d_in[3];
    const float* bvec = (const float*)d_in[4];
    const float* v    = (const float*)d_in[5];
    const float* W_ih = (const float*)d_in[6];
    const float* W_hh = (const float*)d_in[7];
    const float* b_ih = (const float*)d_in[8];
    const float* b_hh = (const float*)d_in[9];
    const float* U_o  = (const float*)d_in[10];
    const float* V_o  = (const float*)d_in[11];
    const float* C_o  = (const float*)d_in[12];
    const float* W_o  = (const float*)d_in[13];
    float* out = (float*)d_out;

    dec_kernel<<<NB, NT>>>(x, Ey_t, W, U, bvec, v, W_ih, W_hh, b_ih, b_hh,
                           U_o, V_o, C_o, W_o, out);
}

// round 3
// speedup vs baseline: 1.4811x; 1.4811x over previous
#include <cuda_runtime.h>
#include <cuda_bf16.h>
#include <math.h>

#define NB 148
#define NT 512
#define KY 32000
typedef __nv_bfloat16 bf;

// ---------------- device scratch ----------------
__device__ __align__(128) bf g_xh[4096*512], g_xl[4096*512];
__device__ __align__(128) bf g_Wph[512*1024], g_Wpl[512*1024];
__device__ __align__(128) bf g_Uph[512*512], g_Upl[512*512];
__device__ __align__(128) bf g_Wihh[3072*512], g_Wihl[3072*512];
__device__ __align__(128) bf g_Whhh[3072*1024], g_Whhl[3072*1024];
__device__ __align__(128) bf g_Uoph[1024*1024], g_Uopl[1024*1024];
__device__ __align__(128) bf g_Voph[1024*512], g_Vopl[1024*512];
__device__ __align__(128) bf g_Coph[1024*512], g_Copl[1024*512];
__device__ __align__(128) bf g_Woph[(size_t)KY*512], g_Wopl[(size_t)KY*512];
__device__ __align__(128) bf g_Eyph[(size_t)512*KY], g_Eypl[(size_t)512*KY];
__device__ __align__(128) bf g_sh[2][64*1024], g_sl[2][64*1024];
__device__ __align__(128) bf g_ctxh[64*512], g_ctxl[64*512];
__device__ __align__(128) bf g_yEh[64*512], g_yEl[64*512];
__device__ __align__(128) bf g_tmh[64*512], g_tml[64*512];
__device__ __align__(128) bf g_evh[(size_t)64*KY], g_evl[(size_t)64*KY];
__device__ __align__(128) float g_sf[2][64*1024];
__device__ __align__(128) float g_Uh[4096*512];
__device__ __align__(128) float g_wsbp[2][64*512];
__device__ __align__(128) float g_e[64*64];
__device__ __align__(128) float g_gip[2][64*3072];
__device__ __align__(128) float g_ghp[4][64*3072];
__device__ __align__(128) float g_tp[8][64*1024];
__device__ __align__(128) float g_lg[(size_t)64*KY];
__device__ __align__(128) float g_yep[25][64*512];
__device__ __align__(128) float g_Zp[64*4];

// ---------------- grid barrier ----------------
__device__ unsigned g_cnt = 0;
__device__ volatile unsigned g_gen = 0;

__device__ __forceinline__ void gsync() {
    __syncthreads();
    if (threadIdx.x == 0) {
        unsigned gen = g_gen;
        __threadfence();
        if (atomicAdd(&g_cnt, 1u) == NB - 1u) {
            atomicExch(&g_cnt, 0u);
            __threadfence();
            g_gen = gen + 1u;
        } else {
            while (g_gen == gen) __nanosleep(64);
            __threadfence();
        }
    }
    __syncthreads();
}

__device__ __forceinline__ float tanh_fast(float x) {
    float y; asm("tanh.approx.f32 %0, %1;" : "=f"(y) : "f"(x)); return y;
}

__device__ __forceinline__ void csplit(float x, bf& h, bf& l) {
    h = __float2bfloat16(x);
    l = __float2bfloat16(x - __bfloat162float(h));
}

#define MMA(d, a0, a1, a2, a3, b0, b1)                                        \
    asm volatile("mma.sync.aligned.m16n8k16.row.col.f32.bf16.bf16.f32 "       \
                 "{%0,%1,%2,%3}, {%4,%5,%6,%7}, {%8,%9}, {%0,%1,%2,%3};"      \
                 : "+f"(d[0]), "+f"(d[1]), "+f"(d[2]), "+f"(d[3])             \
                 : "r"(a0), "r"(a1), "r"(a2), "r"(a3), "r"(b0), "r"(b1))

// ------- bf16-split MMA tile: C[0:64][n0:n0+128] = A[0:64][k0:k0+kc] * B^T -------
// A: [64][lda] bf16 hi/lo row-major. B packed [n][ldb] bf16 hi/lo (n-major, k contiguous).
// C fp32, ldc. kc multiple of 16. Block = 512 threads. Double-buffered smem (24KB).
__device__ __noinline__ void mma_tile(
    const bf* __restrict__ Ah, const bf* __restrict__ Al, int lda,
    const bf* __restrict__ Bh, const bf* __restrict__ Bl, int ldb,
    float* __restrict__ C, int ldc, int n0, int k0, int kc, bf* sm) {
    bf* sAh = sm;          // [2][1024]
    bf* sAl = sm + 2048;   // [2][1024]
    bf* sBh = sm + 4096;   // [2][2048]
    bf* sBl = sm + 8192;   // [2][2048]
    const int tid = threadIdx.x;
    const int am  = (tid & 255) >> 2;
    const int akq = (tid & 3) << 2;
    const int bn  = tid >> 2;
    const int bkq = (tid & 3) << 2;
    const bf* Ap  = ((tid < 256) ? Ah : Al) + (size_t)am * lda + k0 + akq;
    const bf* Bhp = Bh + (size_t)(n0 + bn) * ldb + k0 + bkq;
    const bf* Blp = Bl + (size_t)(n0 + bn) * ldb + k0 + bkq;
    bf* sAdst = ((tid < 256) ? sAh : sAl) + am * 16 + akq;
    bf* sBhd  = sBh + bn * 16 + bkq;
    bf* sBld  = sBl + bn * 16 + bkq;

    const int w = tid >> 5, lane = tid & 31;
    const int mr = (w & 3) << 4, nc = (w >> 2) << 5;
    const int fr = lane >> 2, fc = (lane & 3) << 1;
    const int aoff = (mr + fr) * 16 + fc;
    const int boff = (nc + fr) * 16 + fc;

    float acc[16];
#pragma unroll
    for (int i = 0; i < 16; i++) acc[i] = 0.f;

    uint2 ra  = *(const uint2*)Ap;
    uint2 rbh = *(const uint2*)Bhp;
    uint2 rbl = *(const uint2*)Blp;
    *(uint2*)sAdst = ra;
    *(uint2*)sBhd  = rbh;
    *(uint2*)sBld  = rbl;
    __syncthreads();
    int st = 0;
    for (int ks = 16; ks <= kc; ks += 16) {
        const bool more = ks < kc;
        if (more) {
            Ap += 16; Bhp += 16; Blp += 16;
            ra  = *(const uint2*)Ap;
            rbh = *(const uint2*)Bhp;
            rbl = *(const uint2*)Blp;
        }
        const bf* pah = sAh + st * 1024 + aoff;
        const bf* pal = sAl + st * 1024 + aoff;
        unsigned ah0 = *(const unsigned*)(pah);
        unsigned ah1 = *(const unsigned*)(pah + 128);
        unsigned ah2 = *(const unsigned*)(pah + 8);
        unsigned ah3 = *(const unsigned*)(pah + 136);
        unsigned al0 = *(const unsigned*)(pal);
        unsigned al1 = *(const unsigned*)(pal + 128);
        unsigned al2 = *(const unsigned*)(pal + 8);
        unsigned al3 = *(const unsigned*)(pal + 136);
        const bf* pbh = sBh + st * 2048 + boff;
        const bf* pbl = sBl + st * 2048 + boff;
#pragma unroll
        for (int j = 0; j < 4; j++) {
            unsigned bh0 = *(const unsigned*)(pbh + j * 128);
            unsigned bh1 = *(const unsigned*)(pbh + j * 128 + 8);
            unsigned bl0 = *(const unsigned*)(pbl + j * 128);
            unsigned bl1 = *(const unsigned*)(pbl + j * 128 + 8);
            float* d = acc + j * 4;
            MMA(d, ah0, ah1, ah2, ah3, bh0, bh1);
            MMA(d, ah0, ah1, ah2, ah3, bl0, bl1);
            MMA(d, al0, al1, al2, al3, bh0, bh1);
        }
        if (more) {
            int sn = st ^ 1;
            *(uint2*)(sAdst + sn * 1024) = ra;
            *(uint2*)(sBhd + sn * 2048)  = rbh;
            *(uint2*)(sBld + sn * 2048)  = rbl;
        }
        __syncthreads();
        st ^= 1;
    }
#pragma unroll
    for (int j = 0; j < 4; j++) {
        int col = n0 + nc + j * 8 + fc;
        float* c0 = C + (size_t)(mr + fr) * ldc + col;
        *(float2*)c0 = make_float2(acc[j * 4], acc[j * 4 + 1]);
        *(float2*)(c0 + (size_t)8 * ldc) = make_float2(acc[j * 4 + 2], acc[j * 4 + 3]);
    }
}

// elementwise fp32 -> bf16 hi/lo
__device__ void convN(const float* __restrict__ in, size_t n,
                      bf* __restrict__ oh, bf* __restrict__ ol, size_t gth, size_t gs) {
    for (size_t i = gth; i < n; i += gs) csplit(in[i], oh[i], ol[i]);
}

// tiled transpose-convert: out[c][r] = in[r][c]; R,C mult of 32; sm = 32*33 floats
__device__ void ttconv(const float* __restrict__ in, int R, int Cc,
                       bf* __restrict__ oh, bf* __restrict__ ol, float* sm) {
    int ntr = R >> 5, ntc = Cc >> 5;
    int tx = threadIdx.x & 31, ty = threadIdx.x >> 5;
    for (int tile = blockIdx.x; tile < ntr * ntc; tile += NB) {
        int tr = tile / ntc, tc = tile % ntc;
        int r0 = tr << 5, c0 = tc << 5;
        __syncthreads();
        sm[ty * 33 + tx]        = in[(size_t)(r0 + ty) * Cc + c0 + tx];
        sm[(ty + 16) * 33 + tx] = in[(size_t)(r0 + ty + 16) * Cc + c0 + tx];
        __syncthreads();
        size_t o0 = (size_t)(c0 + ty) * R + r0 + tx;
        size_t o1 = (size_t)(c0 + ty + 16) * R + r0 + tx;
        csplit(sm[tx * 33 + ty], oh[o0], ol[o0]);
        csplit(sm[tx * 33 + ty + 16], oh[o1], ol[o1]);
    }
}

__device__ __forceinline__ float block_sum(float v, float* red) {
#pragma unroll
    for (int o = 16; o > 0; o >>= 1) v += __shfl_down_sync(0xffffffffu, v, o);
    if ((threadIdx.x & 31) == 0) red[threadIdx.x >> 5] = v;
    __syncthreads();
    float r = 0.f;
#pragma unroll
    for (int i = 0; i < 16; i++) r += red[i];
    __syncthreads();
    return r;
}

__global__ __launch_bounds__(NT, 1) void dec_kernel(
    const float* __restrict__ x,    const float* __restrict__ Ey_t,
    const float* __restrict__ W,    const float* __restrict__ U,
    const float* __restrict__ bvec, const float* __restrict__ v,
    const float* __restrict__ W_ih, const float* __restrict__ W_hh,
    const float* __restrict__ b_ih, const float* __restrict__ b_hh,
    const float* __restrict__ U_o,  const float* __restrict__ V_o,
    const float* __restrict__ C_o,  const float* __restrict__ W_o,
    float* __restrict__ out) {
    __shared__ __align__(16) char sraw[24 * 1024];
    __shared__ float s_red[16];
    bf* smb = (bf*)sraw;
    float* smf = (float*)sraw;
    const int tid = threadIdx.x, bid = blockIdx.x;
    const size_t gth = (size_t)bid * NT + tid, GS = (size_t)NB * NT;
    const int lane = tid & 31;
    const bf z0 = __float2bfloat16(0.f);

    // ---- prep wave 0: zeros + weight packing ----
    for (size_t i = gth; i < 64 * 1024; i += GS) {
        g_sf[0][i] = 0.f; g_sh[0][i] = z0; g_sl[0][i] = z0;
    }
    for (size_t i = gth; i < 64 * 512; i += GS) { g_yEh[i] = z0; g_yEl[i] = z0; }
    convN(x, (size_t)4096 * 512, g_xh, g_xl, gth, GS);
    convN(W_ih, (size_t)3072 * 512, g_Wihh, g_Wihl, gth, GS);
    convN(W_hh, (size_t)3072 * 1024, g_Whhh, g_Whhl, gth, GS);
    ttconv(W, 1024, 512, g_Wph, g_Wpl, smf);
    ttconv(U, 512, 512, g_Uph, g_Upl, smf);
    ttconv(U_o, 1024, 1024, g_Uoph, g_Uopl, smf);
    ttconv(V_o, 512, 1024, g_Voph, g_Vopl, smf);
    ttconv(C_o, 512, 1024, g_Coph, g_Copl, smf);
    ttconv(W_o, 512, KY, g_Woph, g_Wopl, smf);
    ttconv(Ey_t, KY, 512, g_Eyph, g_Eypl, smf);
    gsync();

    // ---- prep wave 1: U_h = x @ U (256 jobs) + Wsb(s0) (8 jobs) ----
    for (int j = bid; j < 264; j += NB) {
        if (j < 256) {
            int mt = j >> 2, nt = j & 3;
            mma_tile(g_xh + (size_t)mt * 64 * 512, g_xl + (size_t)mt * 64 * 512, 512,
                     g_Uph, g_Upl, 512,
                     g_Uh + (size_t)mt * 64 * 512, 512, nt * 128, 0, 512, smb);
        } else {
            int q = j - 256, ch = q >> 2, nt = q & 3;
            mma_tile(g_sh[0], g_sl[0], 1024, g_Wph, g_Wpl, 1024,
                     g_wsbp[ch], 512, nt * 128, ch * 512, 512, smb);
        }
    }
    gsync();

    for (int t = 0; t < 64; t++) {
        const int cur = t & 1, nxt = cur ^ 1;

        // ---- B1: attention energies (256 jobs) ----
        for (int j = bid; j < 256; j += NB) {
            int b = j >> 2, jg = j & 3;
            __syncthreads();
            smf[tid] = g_wsbp[0][b * 512 + tid] + g_wsbp[1][b * 512 + tid] + bvec[tid];
            smf[512 + tid] = v[tid];
            __syncthreads();
            int jr = jg * 16 + (tid >> 5);
            const float* uh = g_Uh + (size_t)(b * 64 + jr) * 512;
            float acc = 0.f;
            for (int c = lane; c < 512; c += 32)
                acc += tanh_fast(smf[c] + uh[c]) * smf[512 + c];
#pragma unroll
            for (int o = 16; o > 0; o >>= 1) acc += __shfl_down_sync(0xffffffffu, acc, o);
            if (lane == 0) g_e[b * 64 + jr] = acc;
        }
        gsync();

        // ---- B2: softmax+ctx (bid<64) / yE reduce+scale (bid>=64) ----
        if (bid < 64) {
            int b = bid;
            if (tid < 64) smf[tid] = g_e[b * 64 + tid];
            __syncthreads();
            float mx = -1e30f;
#pragma unroll
            for (int j = 0; j < 64; j++) mx = fmaxf(mx, smf[j]);
            float ex = (tid < 64) ? __expf(smf[tid] - mx) : 0.f;
            __syncthreads();
            if (tid < 64) smf[64 + tid] = ex;
            __syncthreads();
            float Z = 0.f;
#pragma unroll
            for (int j = 0; j < 64; j++) Z += smf[64 + j];
            float inv = 1.f / Z;
            const float* xb = x + (size_t)b * 64 * 512;
            float ca = 0.f;
            for (int j = 0; j < 64; j++) ca += smf[64 + j] * xb[j * 512 + tid];
            csplit(ca * inv, g_ctxh[b * 512 + tid], g_ctxl[b * 512 + tid]);
        } else if (t > 0) {
            for (size_t i = (size_t)(bid - 64) * NT + tid; i < 64 * 512; i += (size_t)84 * NT) {
                int b = (int)(i >> 9);
                float Z = g_Zp[b * 4] + g_Zp[b * 4 + 1] + g_Zp[b * 4 + 2] + g_Zp[b * 4 + 3];
                float s = 0.f;
#pragma unroll
                for (int p = 0; p < 25; p++) s += g_yep[p][i];
                csplit(s / Z, g_yEh[i], g_yEl[i]);
            }
        }
        gsync();

        // ---- C: gi (48 jobs) + gh (96 jobs) ----
        for (int j = bid; j < 144; j += NB) {
            if (j < 48) {
                int ch = j / 24, nt = j % 24;
                mma_tile(g_ctxh, g_ctxl, 512, g_Wihh, g_Wihl, 512,
                         g_gip[ch], 3072, nt * 128, ch * 256, 256, smb);
            } else {
                int q = j - 48, ch = q / 24, nt = q % 24;
                mma_tile(g_sh[cur], g_sl[cur], 1024, g_Whhh, g_Whhl, 1024,
                         g_ghp[ch], 3072, nt * 128, ch * 256, 256, smb);
            }
        }
        gsync();

        // ---- D: gate combine ----
        for (size_t i = gth; i < 64 * 1024; i += GS) {
            int b = (int)(i >> 10), h = (int)(i & 1023);
            size_t bs = (size_t)b * 3072;
            float gr = b_ih[h], gz = b_ih[1024 + h], gn = b_ih[2048 + h];
            float hr = b_hh[h], hz = b_hh[1024 + h], hn = b_hh[2048 + h];
#pragma unroll
            for (int p = 0; p < 2; p++) {
                gr += g_gip[p][bs + h];
                gz += g_gip[p][bs + 1024 + h];
                gn += g_gip[p][bs + 2048 + h];
            }
#pragma unroll
            for (int p = 0; p < 4; p++) {
                hr += g_ghp[p][bs + h];
                hz += g_ghp[p][bs + 1024 + h];
                hn += g_ghp[p][bs + 2048 + h];
            }
            float r = 1.f / (1.f + __expf(-(gr + hr)));
            float zz = 1.f / (1.f + __expf(-(gz + hz)));
            float n = tanhf(gn + r * hn);
            float sn = (1.f - zz) * n + zz * g_sf[cur][i];
            g_sf[nxt][i] = sn;
            csplit(sn, g_sh[nxt][i], g_sl[nxt][i]);
        }
        gsync();

        // ---- E: t partials (64 jobs) ----
        for (int j = bid; j < 64; j += NB) {
            if (j < 32) {
                int ch = j >> 3, nt = j & 7;
                mma_tile(g_sh[nxt], g_sl[nxt], 1024, g_Uoph, g_Uopl, 1024,
                         g_tp[ch], 1024, nt * 128, ch * 256, 256, smb);
            } else if (j < 48) {
                int q = j - 32, ch = q >> 3, nt = q & 7;
                mma_tile(g_yEh, g_yEl, 512, g_Voph, g_Vopl, 512,
                         g_tp[4 + ch], 1024, nt * 128, ch * 256, 256, smb);
            } else {
                int q = j - 48, ch = q >> 3, nt = q & 7;
                mma_tile(g_ctxh, g_ctxl, 512, g_Coph, g_Copl, 512,
                         g_tp[6 + ch], 1024, nt * 128, ch * 256, 256, smb);
            }
        }
        gsync();

        // ---- F: maxout + zero Zp ----
        for (size_t i = gth; i < 64 * 512; i += GS) {
            int b = (int)(i >> 9), d = (int)(i & 511);
            size_t base = (size_t)b * 1024 + 2 * d;
            float t0 = 0.f, t1 = 0.f;
#pragma unroll
            for (int p = 0; p < 8; p++) { t0 += g_tp[p][base]; t1 += g_tp[p][base + 1]; }
            csplit(fmaxf(t0, t1), g_tmh[i], g_tml[i]);
        }
        if (gth < 256) g_Zp[gth] = 0.f;
        gsync();

        // ---- G: logits (250 jobs) + Wsb for t+1 (8 jobs) ----
        for (int j = bid; j < 258; j += NB) {
            if (j < 250) {
                mma_tile(g_tmh, g_tml, 512, g_Woph, g_Wopl, 512,
                         g_lg, KY, j * 128, 0, 512, smb);
            } else {
                int q = j - 250, ch = q >> 2, nt = q & 3;
                mma_tile(g_sh[nxt], g_sl[nxt], 1024, g_Wph, g_Wpl, 1024,
                         g_wsbp[ch], 512, nt * 128, ch * 512, 512, smb);
            }
        }
        gsync();

        // ---- H: exp + partial sums (256 jobs); no max-sub (|logit| small) ----
        for (int j = bid; j < 256; j += NB) {
            int b = j >> 2, q = j & 3;
            float* l = g_lg + (size_t)b * KY;
            float sum = 0.f;
            for (int k = q * 8000 + tid; k < (q + 1) * 8000; k += NT) {
                float e = __expf(l[k]);
                l[k] = e;
                csplit(e, g_evh[(size_t)b * KY + k], g_evl[(size_t)b * KY + k]);
                sum += e;
            }
            sum = block_sum(sum, s_red);
            if (tid == 0) g_Zp[b * 4 + q] = sum;
            __syncthreads();
        }
        gsync();

        // ---- I: yE partials (100 jobs, skip last step) + output scaling ----
        {
            float* po = out + (size_t)t * 64 * KY;
            if (bid < 100) {
                if (t < 63) {
                    int ch = bid >> 2, nt = bid & 3;
                    mma_tile(g_evh, g_evl, KY, g_Eyph, g_Eypl, KY,
                             g_yep[ch], 512, nt * 128, ch * 1280, 1280, smb);
                }
            } else {
                for (int b = bid - 100; b < 64; b += 48) {
                    float Z = g_Zp[b * 4] + g_Zp[b * 4 + 1] + g_Zp[b * 4 + 2] + g_Zp[b * 4 + 3];
                    float inv = 1.f / Z;
                    const float* l = g_lg + (size_t)b * KY;
                    float* pb = po + (size_t)b * KY;
                    for (int k = tid; k < KY; k += NT) pb[k] = l[k] * inv;
                }
            }
        }
        gsync();
    }
}

extern "C" void kernel_launch(void* const* d_in, const int* in_sizes, int n_in,
                              void* d_out, int out_size) {
    const float* x    = (const float*)d_in[0];
    const float* Ey_t = (const float*)d_in[1];
    const float* W    = (const float*)d_in[2];
    const float* U    = (const float*)d_in[3];
    const float* bvec = (const float*)d_in[4];
    const float* v    = (const float*)d_in[5];
    const float* W_ih = (const float*)d_in[6];
    const float* W_hh = (const float*)d_in[7];
    const float* b_ih = (const float*)d_in[8];
    const float* b_hh = (const float*)d_in[9];
    const float* U_o  = (const float*)d_in[10];
    const float* V_o  = (const float*)d_in[11];
    const float* C_o  = (const float*)d_in[12];
    const float* W_o  = (const float*)d_in[13];
    float* out = (float*)d_out;

    dec_kernel<<<NB, NT>>>(x, Ey_t, W, U, bvec, v, W_ih, W_hh, b_ih, b_hh,
                           U_o, V_o, C_o, W_o, out);
}

// round 4
// speedup vs baseline: 2.0753x; 1.4012x over previous
#include <cuda_runtime.h>
#include <cuda_bf16.h>
#include <math.h>

#define NB 148
#define NT 512
#define KY 32000
typedef __nv_bfloat16 bf;

// ---------------- device scratch ----------------
__device__ __align__(128) bf g_xh[4096*512], g_xl[4096*512];
__device__ __align__(128) bf g_Wph[512*1024], g_Wpl[512*1024];
__device__ __align__(128) bf g_Uph[512*512], g_Upl[512*512];
__device__ __align__(128) bf g_Wihh[3072*512], g_Wihl[3072*512];
__device__ __align__(128) bf g_Whhh[3072*1024], g_Whhl[3072*1024];
__device__ __align__(128) bf g_Uoph[1024*1024], g_Uopl[1024*1024];
__device__ __align__(128) bf g_Voph[1024*512], g_Vopl[1024*512];
__device__ __align__(128) bf g_Coph[1024*512], g_Copl[1024*512];
__device__ __align__(128) bf g_Woph[(size_t)KY*512], g_Wopl[(size_t)KY*512];
__device__ __align__(128) bf g_Eyph[(size_t)512*KY], g_Eypl[(size_t)512*KY];
__device__ __align__(128) bf g_sh[2][64*1024], g_sl[2][64*1024];
__device__ __align__(128) bf g_ctxh[64*512], g_ctxl[64*512];
__device__ __align__(128) bf g_yEh[64*512], g_yEl[64*512];
__device__ __align__(128) bf g_tmh[64*512], g_tml[64*512];
__device__ __align__(128) bf g_evh[(size_t)64*KY], g_evl[(size_t)64*KY];
__device__ __align__(128) float g_sf[2][64*1024];
__device__ __align__(128) float g_Uh[4096*512];
__device__ __align__(128) float g_wsbp[2][64*512];
__device__ __align__(128) float g_e[64*64];
__device__ __align__(128) float g_gip[2][64*3072];
__device__ __align__(128) float g_ghp[4][64*3072];
__device__ __align__(128) float g_tp[8][64*1024];
__device__ __align__(128) float g_yep[25][64*512];
__device__ __align__(128) float g_Zt[64*256];
__device__ __align__(128) float g_Zinv[64];

// ---------------- grid barrier ----------------
__device__ unsigned g_cnt = 0;
__device__ volatile unsigned g_gen = 0;

__device__ __forceinline__ void gsync() {
    __syncthreads();
    if (threadIdx.x == 0) {
        unsigned gen = g_gen;
        __threadfence();
        if (atomicAdd(&g_cnt, 1u) == NB - 1u) {
            atomicExch(&g_cnt, 0u);
            __threadfence();
            g_gen = gen + 1u;
        } else {
            while (g_gen == gen) __nanosleep(64);
            __threadfence();
        }
    }
    __syncthreads();
}

__device__ __forceinline__ float tanh_fast(float x) {
    float y; asm("tanh.approx.f32 %0, %1;" : "=f"(y) : "f"(x)); return y;
}

__device__ __forceinline__ void csplit(float x, bf& h, bf& l) {
    h = __float2bfloat16(x);
    l = __float2bfloat16(x - __bfloat162float(h));
}

#define MMA(d, a0, a1, a2, a3, b0, b1)                                        \
    asm volatile("mma.sync.aligned.m16n8k16.row.col.f32.bf16.bf16.f32 "       \
                 "{%0,%1,%2,%3}, {%4,%5,%6,%7}, {%8,%9}, {%0,%1,%2,%3};"      \
                 : "+f"(d[0]), "+f"(d[1]), "+f"(d[2]), "+f"(d[3])             \
                 : "r"(a0), "r"(a1), "r"(a2), "r"(a3), "r"(b0), "r"(b1))

// ------- core: acc[16] = A[0:64][k0:k0+kc] * B^T (3-term bf16 split) -------
// 32-k double-buffered stages, uint4 streaming, padded smem (stride 40).
// smem layout (bf16): sA[st][hl][2560] @0, sB[st][hl][5120] @10240. kc%32==0.
__device__ __forceinline__ void mma_core(
    const bf* __restrict__ Ah, const bf* __restrict__ Al, int lda,
    const bf* __restrict__ Bh, const bf* __restrict__ Bl, int ldb,
    int n0, int k0, int kc, bf* __restrict__ sm, float* acc) {
    const int tid = threadIdx.x;
    bf* sA = sm;
    bf* sB = sm + 10240;
    const int hl  = tid >> 8;
    const int ar  = (tid & 255) >> 2;
    const int akq = (tid & 3) << 3;
    const int bn  = tid >> 2;
    const int bkq = (tid & 3) << 3;
    const bf* Ap  = (hl ? Al : Ah) + (size_t)ar * lda + k0 + akq;
    const bf* Bhp = Bh + (size_t)(n0 + bn) * ldb + k0 + bkq;
    const bf* Blp = Bl + (size_t)(n0 + bn) * ldb + k0 + bkq;
    bf* sAd  = sA + hl * 2560 + ar * 40 + akq;
    bf* sBhd = sB + bn * 40 + bkq;
    bf* sBld = sBhd + 5120;
    const int w = tid >> 5, lane = tid & 31;
    const int mr = (w & 3) << 4, nc = (w >> 2) << 5;
    const int fr = lane >> 2, fc = (lane & 3) << 1;
    const int aoff = (mr + fr) * 40 + fc;
    const int boff = (nc + fr) * 40 + fc;
#pragma unroll
    for (int i = 0; i < 16; i++) acc[i] = 0.f;

    uint4 ra  = *(const uint4*)Ap;
    uint4 rbh = *(const uint4*)Bhp;
    uint4 rbl = *(const uint4*)Blp;
    *(uint4*)sAd = ra; *(uint4*)sBhd = rbh; *(uint4*)sBld = rbl;
    __syncthreads();
    const int ns = kc >> 5;
    int st = 0;
    for (int s = 0; s < ns; s++) {
        if (s + 1 < ns) {
            Ap += 32; Bhp += 32; Blp += 32;
            ra  = *(const uint4*)Ap;
            rbh = *(const uint4*)Bhp;
            rbl = *(const uint4*)Blp;
        }
        const bf* sAb = sA + st * 5120;
        const bf* sBb = sB + st * 10240;
#pragma unroll
        for (int half = 0; half < 2; half++) {
            const int ko = half << 4;
            const bf* pah = sAb + aoff + ko;
            unsigned ah0 = *(const unsigned*)(pah);
            unsigned ah1 = *(const unsigned*)(pah + 320);
            unsigned ah2 = *(const unsigned*)(pah + 8);
            unsigned ah3 = *(const unsigned*)(pah + 328);
            const bf* pal = pah + 2560;
            unsigned al0 = *(const unsigned*)(pal);
            unsigned al1 = *(const unsigned*)(pal + 320);
            unsigned al2 = *(const unsigned*)(pal + 8);
            unsigned al3 = *(const unsigned*)(pal + 328);
            const bf* pbh = sBb + boff + ko;
            const bf* pbl = pbh + 5120;
#pragma unroll
            for (int j = 0; j < 4; j++) {
                unsigned bh0 = *(const unsigned*)(pbh + j * 320);
                unsigned bh1 = *(const unsigned*)(pbh + j * 320 + 8);
                unsigned bl0 = *(const unsigned*)(pbl + j * 320);
                unsigned bl1 = *(const unsigned*)(pbl + j * 320 + 8);
                float* d = acc + j * 4;
                MMA(d, ah0, ah1, ah2, ah3, bh0, bh1);
                MMA(d, ah0, ah1, ah2, ah3, bl0, bl1);
                MMA(d, al0, al1, al2, al3, bh0, bh1);
            }
        }
        if (s + 1 < ns) {
            int sn = st ^ 1;
            *(uint4*)(sAd + sn * 5120)   = ra;
            *(uint4*)(sBhd + sn * 10240) = rbh;
            *(uint4*)(sBld + sn * 10240) = rbl;
        }
        __syncthreads();
        st ^= 1;
    }
}

__device__ __noinline__ void mma_tile(
    const bf* __restrict__ Ah, const bf* __restrict__ Al, int lda,
    const bf* __restrict__ Bh, const bf* __restrict__ Bl, int ldb,
    float* __restrict__ C, int ldc, int n0, int k0, int kc, bf* sm) {
    float acc[16];
    mma_core(Ah, Al, lda, Bh, Bl, ldb, n0, k0, kc, sm, acc);
    const int tid = threadIdx.x;
    const int w = tid >> 5, lane = tid & 31;
    const int mr = (w & 3) << 4, nc = (w >> 2) << 5;
    const int fr = lane >> 2, fc = (lane & 3) << 1;
#pragma unroll
    for (int j = 0; j < 4; j++) {
        int col = n0 + nc + j * 8 + fc;
        float* c0 = C + (size_t)(mr + fr) * ldc + col;
        *(float2*)c0 = make_float2(acc[j*4], acc[j*4+1]);
        *(float2*)(c0 + (size_t)8 * ldc) = make_float2(acc[j*4+2], acc[j*4+3]);
    }
}

// logits tile -> exp (unnormalized) into g_evh/evl + deterministic row sums g_Zt
__device__ __noinline__ void mma_tile_exp(
    const bf* __restrict__ Ah, const bf* __restrict__ Al,
    const bf* __restrict__ Bh, const bf* __restrict__ Bl,
    int n0, bf* sm) {
    float acc[16];
    mma_core(Ah, Al, 512, Bh, Bl, 512, n0, 0, 512, sm, acc);
    const int tid = threadIdx.x;
    const int w = tid >> 5, lane = tid & 31;
    const int mr = (w & 3) << 4, nc = (w >> 2) << 5;
    const int fr = lane >> 2, fc = (lane & 3) << 1;
    float rs0 = 0.f, rs1 = 0.f;
#pragma unroll
    for (int j = 0; j < 4; j++) {
#pragma unroll
        for (int q = 0; q < 2; q++) {
            int col = n0 + nc + j * 8 + fc + q;
            float e0 = __expf(acc[j*4+q]);
            float e1 = __expf(acc[j*4+2+q]);
            rs0 += e0; rs1 += e1;
            size_t i0 = (size_t)(mr + fr) * KY + col;
            size_t i1 = i0 + (size_t)8 * KY;
            csplit(e0, g_evh[i0], g_evl[i0]);
            csplit(e1, g_evh[i1], g_evl[i1]);
        }
    }
    rs0 += __shfl_xor_sync(~0u, rs0, 1); rs0 += __shfl_xor_sync(~0u, rs0, 2);
    rs1 += __shfl_xor_sync(~0u, rs1, 1); rs1 += __shfl_xor_sync(~0u, rs1, 2);
    float* srs = (float*)sm;
    if ((lane & 3) == 0) { srs[w * 16 + fr] = rs0; srs[w * 16 + 8 + fr] = rs1; }
    __syncthreads();
    if (tid < 64) {
        int mg = tid >> 4, rr = tid & 15;
        float z = srs[mg * 16 + rr] + srs[(4 + mg) * 16 + rr] +
                  srs[(8 + mg) * 16 + rr] + srs[(12 + mg) * 16 + rr];
        g_Zt[tid * 256 + (n0 >> 7)] = z;
    }
    __syncthreads();
}

// attention energy job j (b = j>>2, 16 rows of e per job)
__device__ void energy_job(int j, const float* __restrict__ bvec,
                           const float* __restrict__ v, float* smf) {
    int b = j >> 2, jg = j & 3;
    int tid = threadIdx.x, lane = tid & 31;
    __syncthreads();
    smf[tid] = g_wsbp[0][b * 512 + tid] + g_wsbp[1][b * 512 + tid] + bvec[tid];
    smf[512 + tid] = v[tid];
    __syncthreads();
    int jr = jg * 16 + (tid >> 5);
    const float* uh = g_Uh + (size_t)(b * 64 + jr) * 512;
    float acc = 0.f;
    for (int c = lane; c < 512; c += 32)
        acc += tanh_fast(smf[c] + uh[c]) * smf[512 + c];
#pragma unroll
    for (int o = 16; o > 0; o >>= 1) acc += __shfl_down_sync(~0u, acc, o);
    if (lane == 0) g_e[b * 64 + jr] = acc;
}

__device__ __forceinline__ float block_sum(float v, float* red) {
#pragma unroll
    for (int o = 16; o > 0; o >>= 1) v += __shfl_down_sync(0xffffffffu, v, o);
    if ((threadIdx.x & 31) == 0) red[threadIdx.x >> 5] = v;
    __syncthreads();
    float r = 0.f;
#pragma unroll
    for (int i = 0; i < 16; i++) r += red[i];
    __syncthreads();
    return r;
}

// elementwise fp32 -> bf16 hi/lo
__device__ void convN(const float* __restrict__ in, size_t n,
                      bf* __restrict__ oh, bf* __restrict__ ol, size_t gth, size_t gs) {
    for (size_t i = gth; i < n; i += gs) csplit(in[i], oh[i], ol[i]);
}

// tiled transpose-convert: out[c][r] = in[r][c]
__device__ void ttconv(const float* __restrict__ in, int R, int Cc,
                       bf* __restrict__ oh, bf* __restrict__ ol, float* sm) {
    int ntr = R >> 5, ntc = Cc >> 5;
    int tx = threadIdx.x & 31, ty = threadIdx.x >> 5;
    for (int tile = blockIdx.x; tile < ntr * ntc; tile += NB) {
        int tr = tile / ntc, tc = tile % ntc;
        int r0 = tr << 5, c0 = tc << 5;
        __syncthreads();
        sm[ty * 33 + tx]        = in[(size_t)(r0 + ty) * Cc + c0 + tx];
        sm[(ty + 16) * 33 + tx] = in[(size_t)(r0 + ty + 16) * Cc + c0 + tx];
        __syncthreads();
        size_t o0 = (size_t)(c0 + ty) * R + r0 + tx;
        size_t o1 = (size_t)(c0 + ty + 16) * R + r0 + tx;
        csplit(sm[tx * 33 + ty], oh[o0], ol[o0]);
        csplit(sm[tx * 33 + ty + 16], oh[o1], ol[o1]);
    }
}

__global__ __launch_bounds__(NT, 1) void dec_kernel(
    const float* __restrict__ x,    const float* __restrict__ Ey_t,
    const float* __restrict__ W,    const float* __restrict__ U,
    const float* __restrict__ bvec, const float* __restrict__ v,
    const float* __restrict__ W_ih, const float* __restrict__ W_hh,
    const float* __restrict__ b_ih, const float* __restrict__ b_hh,
    const float* __restrict__ U_o,  const float* __restrict__ V_o,
    const float* __restrict__ C_o,  const float* __restrict__ W_o,
    float* __restrict__ out) {
    extern __shared__ __align__(16) char sraw[];
    bf* smb = (bf*)sraw;
    float* smf = (float*)sraw;
    float* s_red = smf + 1024;
    const int tid = threadIdx.x, bid = blockIdx.x;
    const size_t gth = (size_t)bid * NT + tid, GS = (size_t)NB * NT;
    const bf z0 = __float2bfloat16(0.f);

    // ---- prep wave 0: zeros + weight packing ----
    for (size_t i = gth; i < 64 * 1024; i += GS) {
        g_sf[0][i] = 0.f; g_sh[0][i] = z0; g_sl[0][i] = z0;
    }
    for (size_t i = gth; i < 64 * 512; i += GS) { g_yEh[i] = z0; g_yEl[i] = z0; }
    convN(x, (size_t)4096 * 512, g_xh, g_xl, gth, GS);
    convN(W_ih, (size_t)3072 * 512, g_Wihh, g_Wihl, gth, GS);
    convN(W_hh, (size_t)3072 * 1024, g_Whhh, g_Whhl, gth, GS);
    ttconv(W, 1024, 512, g_Wph, g_Wpl, smf);
    ttconv(U, 512, 512, g_Uph, g_Upl, smf);
    ttconv(U_o, 1024, 1024, g_Uoph, g_Uopl, smf);
    ttconv(V_o, 512, 1024, g_Voph, g_Vopl, smf);
    ttconv(C_o, 512, 1024, g_Coph, g_Copl, smf);
    ttconv(W_o, 512, KY, g_Woph, g_Wopl, smf);
    ttconv(Ey_t, KY, 512, g_Eyph, g_Eypl, smf);
    gsync();

    // ---- prep wave 1: U_h = x @ U (256 jobs) + Wsb(s0) (8 jobs) ----
    for (int j = bid; j < 264; j += NB) {
        if (j < 256) {
            int mt = j >> 2, nt = j & 3;
            mma_tile(g_xh + (size_t)mt * 64 * 512, g_xl + (size_t)mt * 64 * 512, 512,
                     g_Uph, g_Upl, 512,
                     g_Uh + (size_t)mt * 64 * 512, 512, nt * 128, 0, 512, smb);
        } else {
            int q = j - 256, ch = q >> 2, nt = q & 3;
            mma_tile(g_sh[0], g_sl[0], 1024, g_Wph, g_Wpl, 1024,
                     g_wsbp[ch], 512, nt * 128, ch * 512, 512, smb);
        }
    }
    gsync();

    // ---- prep wave 2: energies for t=0 ----
    for (int j = bid; j < 256; j += NB) energy_job(j, bvec, v, smf);
    gsync();

    for (int t = 0; t < 64; t++) {
        const int cur = t & 1, nxt = cur ^ 1;

        // ---- B2: softmax+ctx (bid<64) / yE reduce+scale (bid>=64) ----
        if (bid < 64) {
            int b = bid;
            if (tid < 64) smf[tid] = g_e[b * 64 + tid];
            __syncthreads();
            float mx = -1e30f;
#pragma unroll
            for (int j = 0; j < 64; j++) mx = fmaxf(mx, smf[j]);
            float ex = (tid < 64) ? __expf(smf[tid] - mx) : 0.f;
            __syncthreads();
            if (tid < 64) smf[64 + tid] = ex;
            __syncthreads();
            float Z = 0.f;
#pragma unroll
            for (int j = 0; j < 64; j++) Z += smf[64 + j];
            float inv = 1.f / Z;
            const float* xb = x + (size_t)b * 64 * 512;
            float ca = 0.f;
            for (int j = 0; j < 64; j++) ca += smf[64 + j] * xb[j * 512 + tid];
            csplit(ca * inv, g_ctxh[b * 512 + tid], g_ctxl[b * 512 + tid]);
        } else if (t > 0) {
            for (size_t i = (size_t)(bid - 64) * NT + tid; i < 64 * 512; i += (size_t)84 * NT) {
                int b = (int)(i >> 9);
                float s = 0.f;
#pragma unroll
                for (int p = 0; p < 25; p++) s += g_yep[p][i];
                csplit(s * g_Zinv[b], g_yEh[i], g_yEl[i]);
            }
        }
        gsync();

        // ---- C: gi (48 jobs) + gh (96 jobs) ----
        for (int j = bid; j < 144; j += NB) {
            if (j < 48) {
                int ch = j / 24, nt = j % 24;
                mma_tile(g_ctxh, g_ctxl, 512, g_Wihh, g_Wihl, 512,
                         g_gip[ch], 3072, nt * 128, ch * 256, 256, smb);
            } else {
                int q = j - 48, ch = q / 24, nt = q % 24;
                mma_tile(g_sh[cur], g_sl[cur], 1024, g_Whhh, g_Whhl, 1024,
                         g_ghp[ch], 3072, nt * 128, ch * 256, 256, smb);
            }
        }
        gsync();

        // ---- D: gate combine ----
        for (size_t i = gth; i < 64 * 1024; i += GS) {
            int b = (int)(i >> 10), h = (int)(i & 1023);
            size_t bs = (size_t)b * 3072;
            float gr = b_ih[h], gz = b_ih[1024 + h], gn = b_ih[2048 + h];
            float hr = b_hh[h], hz = b_hh[1024 + h], hn = b_hh[2048 + h];
#pragma unroll
            for (int p = 0; p < 2; p++) {
                gr += g_gip[p][bs + h];
                gz += g_gip[p][bs + 1024 + h];
                gn += g_gip[p][bs + 2048 + h];
            }
#pragma unroll
            for (int p = 0; p < 4; p++) {
                hr += g_ghp[p][bs + h];
                hz += g_ghp[p][bs + 1024 + h];
                hn += g_ghp[p][bs + 2048 + h];
            }
            float r = 1.f / (1.f + __expf(-(gr + hr)));
            float zz = 1.f / (1.f + __expf(-(gz + hz)));
            float n = tanhf(gn + r * hn);
            float sn = (1.f - zz) * n + zz * g_sf[cur][i];
            g_sf[nxt][i] = sn;
            csplit(sn, g_sh[nxt][i], g_sl[nxt][i]);
        }
        gsync();

        // ---- E: t partials (64 jobs) ----
        for (int j = bid; j < 64; j += NB) {
            if (j < 32) {
                int ch = j >> 3, nt = j & 7;
                mma_tile(g_sh[nxt], g_sl[nxt], 1024, g_Uoph, g_Uopl, 1024,
                         g_tp[ch], 1024, nt * 128, ch * 256, 256, smb);
            } else if (j < 48) {
                int q = j - 32, ch = q >> 3, nt = q & 7;
                mma_tile(g_yEh, g_yEl, 512, g_Voph, g_Vopl, 512,
                         g_tp[4 + ch], 1024, nt * 128, ch * 256, 256, smb);
            } else {
                int q = j - 48, ch = q >> 3, nt = q & 7;
                mma_tile(g_ctxh, g_ctxl, 512, g_Coph, g_Copl, 512,
                         g_tp[6 + ch], 1024, nt * 128, ch * 256, 256, smb);
            }
        }
        gsync();

        // ---- F: maxout ----
        for (size_t i = gth; i < 64 * 512; i += GS) {
            int b = (int)(i >> 9), d = (int)(i & 511);
            size_t base = (size_t)b * 1024 + 2 * d;
            float t0 = 0.f, t1 = 0.f;
#pragma unroll
            for (int p = 0; p < 8; p++) { t0 += g_tp[p][base]; t1 += g_tp[p][base + 1]; }
            csplit(fmaxf(t0, t1), g_tmh[i], g_tml[i]);
        }
        gsync();

        // ---- G: logits+exp+Zt (250 jobs) + Wsb for t+1 (8 jobs) ----
        for (int j = bid; j < 258; j += NB) {
            if (j < 250) {
                mma_tile_exp(g_tmh, g_tml, g_Woph, g_Wopl, j * 128, smb);
            } else {
                int q = j - 250, ch = q >> 2, nt = q & 3;
                mma_tile(g_sh[nxt], g_sl[nxt], 1024, g_Wph, g_Wpl, 1024,
                         g_wsbp[ch], 512, nt * 128, ch * 512, 512, smb);
            }
        }
        gsync();

        // ---- I': yE MMA (blocks 0-99) | scale+Z + next-step energies (100-147) ----
        {
            float* po = out + (size_t)t * 64 * KY;
            if (bid < 100) {
                if (t < 63) {
                    int ch = bid >> 2, nt = bid & 3;
                    mma_tile(g_evh, g_evl, KY, g_Eyph, g_Eypl, KY,
                             g_yep[ch], 512, nt * 128, ch * 1280, 1280, smb);
                }
            } else {
                for (int b = bid - 100; b < 64; b += 48) {
                    float z = (tid < 250) ? g_Zt[b * 256 + tid] : 0.f;
                    z = block_sum(z, s_red);
                    float inv = 1.f / z;
                    if (tid == 0) g_Zinv[b] = inv;
                    const bf* eh = g_evh + (size_t)b * KY;
                    const bf* el = g_evl + (size_t)b * KY;
                    float* pb = po + (size_t)b * KY;
                    for (int k = tid; k < KY; k += NT)
                        pb[k] = (__bfloat162float(eh[k]) + __bfloat162float(el[k])) * inv;
                    __syncthreads();
                }
                if (t < 63)
                    for (int j = bid - 100; j < 256; j += 48) energy_job(j, bvec, v, smf);
            }
        }
        gsync();
    }
}

extern "C" void kernel_launch(void* const* d_in, const int* in_sizes, int n_in,
                              void* d_out, int out_size) {
    const float* x    = (const float*)d_in[0];
    const float* Ey_t = (const float*)d_in[1];
    const float* W    = (const float*)d_in[2];
    const float* U    = (const float*)d_in[3];
    const float* bvec = (const float*)d_in[4];
    const float* v    = (const float*)d_in[5];
    const float* W_ih = (const float*)d_in[6];
    const float* W_hh = (const float*)d_in[7];
    const float* b_ih = (const float*)d_in[8];
    const float* b_hh = (const float*)d_in[9];
    const float* U_o  = (const float*)d_in[10];
    const float* V_o  = (const float*)d_in[11];
    const float* C_o  = (const float*)d_in[12];
    const float* W_o  = (const float*)d_in[13];
    float* out = (float*)d_out;

    cudaFuncSetAttribute(dec_kernel, cudaFuncAttributeMaxDynamicSharedMemorySize, 65536);
    dec_kernel<<<NB, NT, 61440>>>(x, Ey_t, W, U, bvec, v, W_ih, W_hh, b_ih, b_hh,
                                  U_o, V_o, C_o, W_o, out);
}